// round 1
// baseline (speedup 1.0000x reference)
#include <cuda_runtime.h>

#define SEQ   2048
#define BATCH 4
#define NTOK  (SEQ * BATCH)      // 8192
#define DIM   1024
#define NH    16
#define HD    64

// ---------------- scratch (device globals per allocation rules) -------------
__device__ float g_xpe [NTOK * DIM];
__device__ float g_q   [NTOK * DIM];
__device__ float g_k   [NTOK * DIM];
__device__ float g_v   [NTOK * DIM];
__device__ float g_attn[NTOK * DIM];
__device__ float g_proj[NTOK * DIM];

// ---------------- x + pe ----------------------------------------------------
__global__ void k_addpe(const float* __restrict__ x, const float* __restrict__ pe) {
    int idx = blockIdx.x * 256 + threadIdx.x;        // float4 index, 2M total
    const float4* x4  = (const float4*)x;
    const float4* pe4 = (const float4*)pe;
    float4*       o4  = (float4*)g_xpe;
    int row = idx >> 8;                               // / (1024/4)
    int c   = idx & 255;
    int s   = row & (SEQ - 1);
    float4 a = x4[idx];
    float4 b = pe4[s * 256 + c];
    a.x += b.x; a.y += b.y; a.z += b.z; a.w += b.w;
    o4[idx] = a;
}

// ---------------- GEMM: C[M,N] = A[M,K] @ B[K,N] + bias ---------------------
// M=8192, N=K=1024. 128x128 block tile, BK=8, 256 threads, 8x8 per thread.
__global__ __launch_bounds__(256) void k_gemm_bias(
    const float* __restrict__ A, const float* __restrict__ B,
    const float* __restrict__ bias, float* __restrict__ C)
{
    __shared__ float As[8][128];
    __shared__ float Bs[8][128];

    const int tid = threadIdx.x;
    const int tx  = tid & 15;
    const int ty  = tid >> 4;
    const int rowBase = blockIdx.y * 128;
    const int colBase = blockIdx.x * 128;

    const int aRow = tid >> 1;            // 0..127
    const int aF4  = (tid & 1) * 4;       // 0 or 4
    const int bK   = tid >> 5;            // 0..7
    const int bC   = (tid & 31) * 4;      // 0..124

    float acc[8][8];
    #pragma unroll
    for (int i = 0; i < 8; i++)
        #pragma unroll
        for (int j = 0; j < 8; j++) acc[i][j] = 0.f;

    for (int k0 = 0; k0 < DIM; k0 += 8) {
        float4 av = *(const float4*)&A[(size_t)(rowBase + aRow) * DIM + k0 + aF4];
        float4 bv = *(const float4*)&B[(size_t)(k0 + bK) * DIM + colBase + bC];
        As[aF4 + 0][aRow] = av.x;
        As[aF4 + 1][aRow] = av.y;
        As[aF4 + 2][aRow] = av.z;
        As[aF4 + 3][aRow] = av.w;
        *(float4*)&Bs[bK][bC] = bv;
        __syncthreads();

        #pragma unroll
        for (int kk = 0; kk < 8; kk++) {
            float a[8], b[8];
            *(float4*)(a)     = *(float4*)&As[kk][ty * 8];
            *(float4*)(a + 4) = *(float4*)&As[kk][ty * 8 + 4];
            *(float4*)(b)     = *(float4*)&Bs[kk][tx * 8];
            *(float4*)(b + 4) = *(float4*)&Bs[kk][tx * 8 + 4];
            #pragma unroll
            for (int i = 0; i < 8; i++)
                #pragma unroll
                for (int j = 0; j < 8; j++)
                    acc[i][j] += a[i] * b[j];
        }
        __syncthreads();
    }

    #pragma unroll
    for (int i = 0; i < 8; i++) {
        int r = rowBase + ty * 8 + i;
        #pragma unroll
        for (int j = 0; j < 8; j += 4) {
            int c = colBase + tx * 8 + j;
            float4 o;
            o.x = acc[i][j]     + bias[c];
            o.y = acc[i][j + 1] + bias[c + 1];
            o.z = acc[i][j + 2] + bias[c + 2];
            o.w = acc[i][j + 3] + bias[c + 3];
            *(float4*)&C[(size_t)r * DIM + c] = o;
        }
    }
}

// ---------------- flash attention -------------------------------------------
// grid: (S/64, NH, BATCH); block: 128 threads. Thread pair (2q,2q+1) owns one
// query: each thread holds 32 of 64 dims; score halves combined via shfl_xor(1).
__global__ __launch_bounds__(128) void k_attn()
{
    __shared__ float Ks[64][64];
    __shared__ float Vs[64][64];

    const int tid  = threadIdx.x;
    const int qt   = blockIdx.x;
    const int h    = blockIdx.y;
    const int b    = blockIdx.z;
    const int q    = tid >> 1;            // 0..63 local query
    const int half = tid & 1;
    const int dbase = half * 32;

    const int qrow = b * SEQ + qt * 64 + q;
    const float* Qp = g_q + (size_t)qrow * DIM + h * HD + dbase;

    float qr[32];
    #pragma unroll
    for (int i = 0; i < 32; i += 4)
        *(float4*)&qr[i] = *(const float4*)&Qp[i];
    #pragma unroll
    for (int i = 0; i < 32; i++) qr[i] *= 0.125f;   // 1/sqrt(64)

    float Oacc[32];
    #pragma unroll
    for (int i = 0; i < 32; i++) Oacc[i] = 0.f;
    float m = -1e30f, l = 0.f;

    const size_t kvbase = (size_t)(b * SEQ) * DIM + h * HD;

    for (int kt = 0; kt < SEQ / 64; kt++) {
        #pragma unroll
        for (int i = 0; i < 8; i++) {
            int f   = i * 128 + tid;
            int key = f >> 4;
            int d4  = (f & 15) * 4;
            size_t g = kvbase + (size_t)(kt * 64 + key) * DIM + d4;
            *(float4*)&Ks[key][d4] = *(const float4*)&g_k[g];
            *(float4*)&Vs[key][d4] = *(const float4*)&g_v[g];
        }
        __syncthreads();

        float sc[64];
        #pragma unroll
        for (int key = 0; key < 64; key++) {
            float s = 0.f;
            #pragma unroll
            for (int i = 0; i < 32; i += 4) {
                float4 kv = *(float4*)&Ks[key][dbase + i];
                s += qr[i] * kv.x + qr[i + 1] * kv.y + qr[i + 2] * kv.z + qr[i + 3] * kv.w;
            }
            s += __shfl_xor_sync(0xffffffffu, s, 1);
            sc[key] = s;
        }

        float mt = m;
        #pragma unroll
        for (int key = 0; key < 64; key++) mt = fmaxf(mt, sc[key]);
        float corr = __expf(m - mt);
        l *= corr;
        #pragma unroll
        for (int i = 0; i < 32; i++) Oacc[i] *= corr;

        #pragma unroll
        for (int key = 0; key < 64; key++) {
            float p = __expf(sc[key] - mt);
            l += p;
            #pragma unroll
            for (int i = 0; i < 32; i += 4) {
                float4 vv = *(float4*)&Vs[key][dbase + i];
                Oacc[i]     += p * vv.x;
                Oacc[i + 1] += p * vv.y;
                Oacc[i + 2] += p * vv.z;
                Oacc[i + 3] += p * vv.w;
            }
        }
        m = mt;
        __syncthreads();
    }

    float inv = 1.f / l;
    float* Op = g_attn + (size_t)qrow * DIM + h * HD + dbase;
    #pragma unroll
    for (int i = 0; i < 32; i += 4) {
        float4 o;
        o.x = Oacc[i]     * inv;
        o.y = Oacc[i + 1] * inv;
        o.z = Oacc[i + 2] * inv;
        o.w = Oacc[i + 3] * inv;
        *(float4*)&Op[i] = o;
    }
}

// ---------------- residual + layernorm ---------------------------------------
__global__ __launch_bounds__(256) void k_ln(const float* __restrict__ gamma,
                                            const float* __restrict__ beta,
                                            float* __restrict__ out)
{
    __shared__ float ws[8], wss[8];
    const int row = blockIdx.x;
    const int tid = threadIdx.x;

    const float4* p4 = (const float4*)(g_proj + (size_t)row * DIM);
    const float4* x4 = (const float4*)(g_xpe  + (size_t)row * DIM);
    float4 a = p4[tid];
    float4 b = x4[tid];
    float4 hv = make_float4(a.x + b.x, a.y + b.y, a.z + b.z, a.w + b.w);

    float s  = hv.x + hv.y + hv.z + hv.w;
    float ss = hv.x * hv.x + hv.y * hv.y + hv.z * hv.z + hv.w * hv.w;
    #pragma unroll
    for (int o = 16; o; o >>= 1) {
        s  += __shfl_xor_sync(0xffffffffu, s,  o);
        ss += __shfl_xor_sync(0xffffffffu, ss, o);
    }
    int w = tid >> 5;
    if ((tid & 31) == 0) { ws[w] = s; wss[w] = ss; }
    __syncthreads();

    float ts = 0.f, tss = 0.f;
    #pragma unroll
    for (int i = 0; i < 8; i++) { ts += ws[i]; tss += wss[i]; }
    float mean = ts * (1.f / 1024.f);
    float var  = tss * (1.f / 1024.f) - mean * mean;
    float rstd = rsqrtf(var + 1e-5f);

    float4 g  = ((const float4*)gamma)[tid];
    float4 be = ((const float4*)beta)[tid];
    float4 o;
    o.x = (hv.x - mean) * rstd * g.x + be.x;
    o.y = (hv.y - mean) * rstd * g.y + be.y;
    o.z = (hv.z - mean) * rstd * g.z + be.z;
    o.w = (hv.w - mean) * rstd * g.w + be.w;
    ((float4*)out)[(size_t)row * 256 + tid] = o;
}

// ---------------- launch ------------------------------------------------------
extern "C" void kernel_launch(void* const* d_in, const int* in_sizes, int n_in,
                              void* d_out, int out_size)
{
    const float* x     = (const float*)d_in[0];
    const float* wq    = (const float*)d_in[1];
    const float* bq    = (const float*)d_in[2];
    const float* wk    = (const float*)d_in[3];
    const float* bk    = (const float*)d_in[4];
    const float* wv    = (const float*)d_in[5];
    const float* bv    = (const float*)d_in[6];
    const float* wo    = (const float*)d_in[7];
    const float* bo    = (const float*)d_in[8];
    const float* gamma = (const float*)d_in[9];
    const float* beta  = (const float*)d_in[10];
    const float* pe    = (const float*)d_in[11];
    float* out = (float*)d_out;

    void *pxpe, *pq, *pk, *pv, *pattn, *pproj;
    cudaGetSymbolAddress(&pxpe,  g_xpe);
    cudaGetSymbolAddress(&pq,    g_q);
    cudaGetSymbolAddress(&pk,    g_k);
    cudaGetSymbolAddress(&pv,    g_v);
    cudaGetSymbolAddress(&pattn, g_attn);
    cudaGetSymbolAddress(&pproj, g_proj);

    k_addpe<<<(NTOK * DIM / 4) / 256, 256>>>(x, pe);

    dim3 ggrid(DIM / 128, NTOK / 128);           // (8, 64)
    k_gemm_bias<<<ggrid, 256>>>((const float*)pxpe, wq, bq, (float*)pq);
    k_gemm_bias<<<ggrid, 256>>>((const float*)pxpe, wk, bk, (float*)pk);
    k_gemm_bias<<<ggrid, 256>>>((const float*)pxpe, wv, bv, (float*)pv);

    dim3 agrid(SEQ / 64, NH, BATCH);             // (32, 16, 4)
    k_attn<<<agrid, 128>>>();

    k_gemm_bias<<<ggrid, 256>>>((const float*)pattn, wo, bo, (float*)pproj);

    k_ln<<<NTOK, 256>>>(gamma, beta, out);
}

// round 3
// speedup vs baseline: 4.6283x; 4.6283x over previous
#include <cuda_runtime.h>
#include <cstdint>

#define SEQ   2048
#define BATCH 4
#define NTOK  (SEQ * BATCH)      // 8192
#define DIM   1024
#define NH    16
#define HD    64

// ---------------- scratch (device globals per allocation rules) -------------
__device__ float g_xpe [NTOK * DIM];
__device__ float g_q   [NTOK * DIM];
__device__ float g_k   [NTOK * DIM];
__device__ float g_v   [NTOK * DIM];
__device__ float g_attn[NTOK * DIM];
__device__ float g_proj[NTOK * DIM];
__device__ float g_wT  [4][DIM * DIM];   // transposed weights [N,K]

// ---------------- mma helpers (base-target safe: sm_80+ PTX) -----------------
__device__ __forceinline__ uint32_t f2tf32(float f) {
    uint32_t r;
    asm("cvt.rna.tf32.f32 %0, %1;" : "=r"(r) : "f"(f));
    return r;
}
__device__ __forceinline__ void mma_tf32(float* d, const uint32_t* a, const uint32_t* b) {
    asm volatile(
        "mma.sync.aligned.m16n8k8.row.col.f32.tf32.tf32.f32 "
        "{%0,%1,%2,%3}, {%4,%5,%6,%7}, {%8,%9}, {%0,%1,%2,%3};\n"
        : "+f"(d[0]), "+f"(d[1]), "+f"(d[2]), "+f"(d[3])
        : "r"(a[0]), "r"(a[1]), "r"(a[2]), "r"(a[3]), "r"(b[0]), "r"(b[1]));
}

// ---------------- x + pe ----------------------------------------------------
__global__ void k_addpe(const float* __restrict__ x, const float* __restrict__ pe) {
    int idx = blockIdx.x * 256 + threadIdx.x;
    const float4* x4  = (const float4*)x;
    const float4* pe4 = (const float4*)pe;
    float4*       o4  = (float4*)g_xpe;
    int row = idx >> 8;
    int c   = idx & 255;
    int s   = row & (SEQ - 1);
    float4 a = x4[idx];
    float4 b = pe4[s * 256 + c];
    a.x += b.x; a.y += b.y; a.z += b.z; a.w += b.w;
    o4[idx] = a;
}

// ---------------- weight transpose: out[n,k] = in[k,n] ----------------------
__global__ __launch_bounds__(256) void k_transpose(const float* __restrict__ in,
                                                   float* __restrict__ out) {
    __shared__ float t[32][33];
    int n0 = blockIdx.x * 32, k0 = blockIdx.y * 32;
    int tx = threadIdx.x & 31, ty = threadIdx.x >> 5;   // 32 x 8
    #pragma unroll
    for (int i = ty; i < 32; i += 8)
        t[i][tx] = in[(size_t)(k0 + i) * DIM + n0 + tx];
    __syncthreads();
    #pragma unroll
    for (int i = ty; i < 32; i += 8)
        out[(size_t)(n0 + i) * DIM + k0 + tx] = t[tx][i];
}

// ---------------- tf32 mma GEMM: C[M,N] = A[M,K] @ Bt[N,K]^T + bias ---------
// 128x128 CTA tile, BK=32, 8 warps (4x2), warp tile 32x64, double-buffered.
#define GPAD  36
#define GTILE (128 * GPAD)                 // words per tile
#define GSMEM (4 * GTILE * 4)              // 73728 bytes

__global__ __launch_bounds__(256) void k_gemm_mma(
    const float* __restrict__ A, const float* __restrict__ Bt,
    const float* __restrict__ bias, float* __restrict__ C)
{
    extern __shared__ uint32_t sm[];
    const int tid  = threadIdx.x;
    const int lane = tid & 31;
    const int wid  = tid >> 5;
    const int wr   = wid & 3;              // warp row (32 rows each)
    const int wc   = wid >> 2;             // warp col (64 cols each)
    const int rowBase = blockIdx.y * 128;
    const int colBase = blockIdx.x * 128;

    const float* Ab = A  + (size_t)rowBase * DIM;
    const float* Bb = Bt + (size_t)colBase * DIM;

    float acc[2][8][4];
    #pragma unroll
    for (int mt = 0; mt < 2; mt++)
        #pragma unroll
        for (int nt = 0; nt < 8; nt++)
            #pragma unroll
            for (int j = 0; j < 4; j++) acc[mt][nt][j] = 0.f;

    float4 stA[4], stB[4];

    auto ldg = [&](int chunk) {
        #pragma unroll
        for (int i = 0; i < 4; i++) {
            int idx = i * 256 + tid;
            int r = idx >> 3, c4 = idx & 7;
            stA[i] = *(const float4*)(Ab + (size_t)r * DIM + chunk * 32 + c4 * 4);
            stB[i] = *(const float4*)(Bb + (size_t)r * DIM + chunk * 32 + c4 * 4);
        }
    };
    auto sts = [&](int buf) {
        uint32_t* as_ = sm + buf * 2 * GTILE;
        uint32_t* bs_ = as_ + GTILE;
        #pragma unroll
        for (int i = 0; i < 4; i++) {
            int idx = i * 256 + tid;
            int r = idx >> 3, c4 = idx & 7;
            uint4 ua = make_uint4(f2tf32(stA[i].x), f2tf32(stA[i].y),
                                  f2tf32(stA[i].z), f2tf32(stA[i].w));
            uint4 ub = make_uint4(f2tf32(stB[i].x), f2tf32(stB[i].y),
                                  f2tf32(stB[i].z), f2tf32(stB[i].w));
            *(uint4*)(as_ + r * GPAD + c4 * 4) = ua;
            *(uint4*)(bs_ + r * GPAD + c4 * 4) = ub;
        }
    };
    auto compute = [&](int buf) {
        const uint32_t* as_ = sm + buf * 2 * GTILE;
        const uint32_t* bs_ = as_ + GTILE;
        #pragma unroll
        for (int kk = 0; kk < 32; kk += 8) {
            uint32_t af[2][4];
            #pragma unroll
            for (int mt = 0; mt < 2; mt++) {
                int r = wr * 32 + mt * 16 + (lane >> 2);
                int c = kk + (lane & 3);
                af[mt][0] = as_[r * GPAD + c];
                af[mt][1] = as_[(r + 8) * GPAD + c];
                af[mt][2] = as_[r * GPAD + c + 4];
                af[mt][3] = as_[(r + 8) * GPAD + c + 4];
            }
            #pragma unroll
            for (int nt = 0; nt < 8; nt++) {
                int n = wc * 64 + nt * 8 + (lane >> 2);
                uint32_t bf[2];
                bf[0] = bs_[n * GPAD + kk + (lane & 3)];
                bf[1] = bs_[n * GPAD + kk + (lane & 3) + 4];
                mma_tf32(acc[0][nt], af[0], bf);
                mma_tf32(acc[1][nt], af[1], bf);
            }
        }
    };

    ldg(0); sts(0);
    __syncthreads();
    for (int c = 0; c < DIM / 32; c++) {
        int b = c & 1;
        if (c + 1 < DIM / 32) ldg(c + 1);
        compute(b);
        if (c + 1 < DIM / 32) sts(b ^ 1);
        __syncthreads();
    }

    #pragma unroll
    for (int mt = 0; mt < 2; mt++) {
        int r = rowBase + wr * 32 + mt * 16 + (lane >> 2);
        #pragma unroll
        for (int nt = 0; nt < 8; nt++) {
            int col = colBase + wc * 64 + nt * 8 + 2 * (lane & 3);
            float2 b2 = *(const float2*)&bias[col];
            float2 o0 = make_float2(acc[mt][nt][0] + b2.x, acc[mt][nt][1] + b2.y);
            float2 o1 = make_float2(acc[mt][nt][2] + b2.x, acc[mt][nt][3] + b2.y);
            *(float2*)&C[(size_t)r * DIM + col]       = o0;
            *(float2*)&C[(size_t)(r + 8) * DIM + col] = o1;
        }
    }
}

// ---------------- flash attention via mma -----------------------------------
// block: 4 warps, 64 queries; warp owns 16 q-rows. kt loop over 64-key tiles.
#define QS    68
#define VSP   72
#define ASMEM ((3 * 64 * QS + 64 * VSP) * 4)   // 70656 bytes

__global__ __launch_bounds__(128) void k_attn_mma()
{
    extern __shared__ uint32_t sm[];
    uint32_t* Qs = sm;
    uint32_t* Ks = sm + 64 * QS;
    uint32_t* Ps = sm + 2 * 64 * QS;
    uint32_t* Vs = sm + 3 * 64 * QS;

    const int tid  = threadIdx.x;
    const int lane = tid & 31;
    const int wid  = tid >> 5;
    const int qt = blockIdx.x, h = blockIdx.y, b = blockIdx.z;
    const size_t qbase  = (size_t)(b * SEQ + qt * 64);
    const size_t kvbase = (size_t)(b * SEQ) * DIM + h * 64;

    // load Q once, pre-scaled by 1/sqrt(64)
    #pragma unroll
    for (int i = 0; i < 8; i++) {
        int idx = i * 128 + tid;
        int r = idx >> 4, c4 = idx & 15;
        float4 v = *(const float4*)(g_q + (qbase + r) * DIM + h * 64 + c4 * 4);
        uint4 u = make_uint4(f2tf32(v.x * 0.125f), f2tf32(v.y * 0.125f),
                             f2tf32(v.z * 0.125f), f2tf32(v.w * 0.125f));
        *(uint4*)(Qs + r * QS + c4 * 4) = u;
    }

    float Oa[8][4];
    #pragma unroll
    for (int nt = 0; nt < 8; nt++)
        #pragma unroll
        for (int j = 0; j < 4; j++) Oa[nt][j] = 0.f;
    float m0 = -1e30f, m1 = -1e30f, l0 = 0.f, l1 = 0.f;

    for (int kt = 0; kt < SEQ / 64; kt++) {
        __syncthreads();
        #pragma unroll
        for (int i = 0; i < 8; i++) {
            int idx = i * 128 + tid;
            int r = idx >> 4, c4 = idx & 15;
            size_t g = kvbase + (size_t)(kt * 64 + r) * DIM + c4 * 4;
            float4 kv = *(const float4*)(g_k + g);
            float4 vv = *(const float4*)(g_v + g);
            *(uint4*)(Ks + r * QS + c4 * 4) =
                make_uint4(f2tf32(kv.x), f2tf32(kv.y), f2tf32(kv.z), f2tf32(kv.w));
            *(uint4*)(Vs + r * VSP + c4 * 4) =
                make_uint4(f2tf32(vv.x), f2tf32(vv.y), f2tf32(vv.z), f2tf32(vv.w));
        }
        __syncthreads();

        // S = Q @ K^T   (warp m-tile = 16 q rows, 64 keys)
        float Sa[8][4];
        #pragma unroll
        for (int nt = 0; nt < 8; nt++)
            #pragma unroll
            for (int j = 0; j < 4; j++) Sa[nt][j] = 0.f;
        #pragma unroll
        for (int kk = 0; kk < 64; kk += 8) {
            uint32_t af[4];
            int r = wid * 16 + (lane >> 2);
            int c = kk + (lane & 3);
            af[0] = Qs[r * QS + c];
            af[1] = Qs[(r + 8) * QS + c];
            af[2] = Qs[r * QS + c + 4];
            af[3] = Qs[(r + 8) * QS + c + 4];
            #pragma unroll
            for (int nt = 0; nt < 8; nt++) {
                int n = nt * 8 + (lane >> 2);
                uint32_t bf[2];
                bf[0] = Ks[n * QS + kk + (lane & 3)];
                bf[1] = Ks[n * QS + kk + (lane & 3) + 4];
                mma_tf32(Sa[nt], af, bf);
            }
        }

        // online softmax (rows r0=wid*16+lane/4, r1=r0+8; row spread over quad)
        float mx0 = m0, mx1 = m1;
        #pragma unroll
        for (int nt = 0; nt < 8; nt++) {
            mx0 = fmaxf(mx0, fmaxf(Sa[nt][0], Sa[nt][1]));
            mx1 = fmaxf(mx1, fmaxf(Sa[nt][2], Sa[nt][3]));
        }
        #pragma unroll
        for (int o = 1; o <= 2; o <<= 1) {
            mx0 = fmaxf(mx0, __shfl_xor_sync(0xffffffffu, mx0, o));
            mx1 = fmaxf(mx1, __shfl_xor_sync(0xffffffffu, mx1, o));
        }
        float corr0 = __expf(m0 - mx0);
        float corr1 = __expf(m1 - mx1);
        m0 = mx0; m1 = mx1;

        float s0 = 0.f, s1 = 0.f;
        int pr = wid * 16 + (lane >> 2);
        #pragma unroll
        for (int nt = 0; nt < 8; nt++) {
            float p00 = __expf(Sa[nt][0] - m0);
            float p01 = __expf(Sa[nt][1] - m0);
            float p10 = __expf(Sa[nt][2] - m1);
            float p11 = __expf(Sa[nt][3] - m1);
            s0 += p00 + p01; s1 += p10 + p11;
            int col = nt * 8 + 2 * (lane & 3);
            Ps[pr * QS + col]           = f2tf32(p00);
            Ps[pr * QS + col + 1]       = f2tf32(p01);
            Ps[(pr + 8) * QS + col]     = f2tf32(p10);
            Ps[(pr + 8) * QS + col + 1] = f2tf32(p11);
        }
        #pragma unroll
        for (int o = 1; o <= 2; o <<= 1) {
            s0 += __shfl_xor_sync(0xffffffffu, s0, o);
            s1 += __shfl_xor_sync(0xffffffffu, s1, o);
        }
        l0 = l0 * corr0 + s0;
        l1 = l1 * corr1 + s1;
        #pragma unroll
        for (int nt = 0; nt < 8; nt++) {
            Oa[nt][0] *= corr0; Oa[nt][1] *= corr0;
            Oa[nt][2] *= corr1; Oa[nt][3] *= corr1;
        }
        __syncwarp();

        // O += P @ V  (A = Ps own-warp rows, B = Vs natural layout)
        #pragma unroll
        for (int kk = 0; kk < 64; kk += 8) {
            uint32_t af[4];
            int r = wid * 16 + (lane >> 2);
            int c = kk + (lane & 3);
            af[0] = Ps[r * QS + c];
            af[1] = Ps[(r + 8) * QS + c];
            af[2] = Ps[r * QS + c + 4];
            af[3] = Ps[(r + 8) * QS + c + 4];
            #pragma unroll
            for (int nt = 0; nt < 8; nt++) {
                uint32_t bf[2];
                bf[0] = Vs[(kk + (lane & 3)) * VSP + nt * 8 + (lane >> 2)];
                bf[1] = Vs[(kk + (lane & 3) + 4) * VSP + nt * 8 + (lane >> 2)];
                mma_tf32(Oa[nt], af, bf);
            }
        }
        __syncwarp();
    }

    float inv0 = 1.f / l0, inv1 = 1.f / l1;
    size_t r = qbase + wid * 16 + (lane >> 2);
    #pragma unroll
    for (int nt = 0; nt < 8; nt++) {
        int col = h * 64 + nt * 8 + 2 * (lane & 3);
        *(float2*)&g_attn[r * DIM + col] =
            make_float2(Oa[nt][0] * inv0, Oa[nt][1] * inv0);
        *(float2*)&g_attn[(r + 8) * DIM + col] =
            make_float2(Oa[nt][2] * inv1, Oa[nt][3] * inv1);
    }
}

// ---------------- residual + layernorm ---------------------------------------
__global__ __launch_bounds__(256) void k_ln(const float* __restrict__ gamma,
                                            const float* __restrict__ beta,
                                            float* __restrict__ out)
{
    __shared__ float ws[8], wss[8];
    const int row = blockIdx.x;
    const int tid = threadIdx.x;

    const float4* p4 = (const float4*)(g_proj + (size_t)row * DIM);
    const float4* x4 = (const float4*)(g_xpe  + (size_t)row * DIM);
    float4 a = p4[tid];
    float4 b = x4[tid];
    float4 hv = make_float4(a.x + b.x, a.y + b.y, a.z + b.z, a.w + b.w);

    float s  = hv.x + hv.y + hv.z + hv.w;
    float ss = hv.x * hv.x + hv.y * hv.y + hv.z * hv.z + hv.w * hv.w;
    #pragma unroll
    for (int o = 16; o; o >>= 1) {
        s  += __shfl_xor_sync(0xffffffffu, s,  o);
        ss += __shfl_xor_sync(0xffffffffu, ss, o);
    }
    int w = tid >> 5;
    if ((tid & 31) == 0) { ws[w] = s; wss[w] = ss; }
    __syncthreads();

    float ts = 0.f, tss = 0.f;
    #pragma unroll
    for (int i = 0; i < 8; i++) { ts += ws[i]; tss += wss[i]; }
    float mean = ts * (1.f / 1024.f);
    float var  = tss * (1.f / 1024.f) - mean * mean;
    float rstd = rsqrtf(var + 1e-5f);

    float4 g  = ((const float4*)gamma)[tid];
    float4 be = ((const float4*)beta)[tid];
    float4 o;
    o.x = (hv.x - mean) * rstd * g.x + be.x;
    o.y = (hv.y - mean) * rstd * g.y + be.y;
    o.z = (hv.z - mean) * rstd * g.z + be.z;
    o.w = (hv.w - mean) * rstd * g.w + be.w;
    ((float4*)out)[(size_t)row * 256 + tid] = o;
}

// ---------------- launch ------------------------------------------------------
extern "C" void kernel_launch(void* const* d_in, const int* in_sizes, int n_in,
                              void* d_out, int out_size)
{
    const float* x     = (const float*)d_in[0];
    const float* wq    = (const float*)d_in[1];
    const float* bq    = (const float*)d_in[2];
    const float* wk    = (const float*)d_in[3];
    const float* bk    = (const float*)d_in[4];
    const float* wv    = (const float*)d_in[5];
    const float* bv    = (const float*)d_in[6];
    const float* wo    = (const float*)d_in[7];
    const float* bo    = (const float*)d_in[8];
    const float* gamma = (const float*)d_in[9];
    const float* beta  = (const float*)d_in[10];
    const float* pe    = (const float*)d_in[11];
    float* out = (float*)d_out;

    void *pxpe, *pq, *pk, *pv, *pattn, *pproj, *pwT;
    cudaGetSymbolAddress(&pxpe,  g_xpe);
    cudaGetSymbolAddress(&pq,    g_q);
    cudaGetSymbolAddress(&pk,    g_k);
    cudaGetSymbolAddress(&pv,    g_v);
    cudaGetSymbolAddress(&pattn, g_attn);
    cudaGetSymbolAddress(&pproj, g_proj);
    cudaGetSymbolAddress(&pwT,   g_wT);
    float* wT = (float*)pwT;

    cudaFuncSetAttribute(k_gemm_mma, cudaFuncAttributeMaxDynamicSharedMemorySize, GSMEM);
    cudaFuncSetAttribute(k_attn_mma, cudaFuncAttributeMaxDynamicSharedMemorySize, ASMEM);

    k_addpe<<<(NTOK * DIM / 4) / 256, 256>>>(x, pe);

    dim3 tgrid(DIM / 32, DIM / 32);
    k_transpose<<<tgrid, 256>>>(wq, wT + 0 * DIM * DIM);
    k_transpose<<<tgrid, 256>>>(wk, wT + 1 * DIM * DIM);
    k_transpose<<<tgrid, 256>>>(wv, wT + 2 * DIM * DIM);
    k_transpose<<<tgrid, 256>>>(wo, wT + 3 * DIM * DIM);

    dim3 ggrid(DIM / 128, NTOK / 128);           // (8, 64)
    k_gemm_mma<<<ggrid, 256, GSMEM>>>((const float*)pxpe, wT + 0 * DIM * DIM, bq, (float*)pq);
    k_gemm_mma<<<ggrid, 256, GSMEM>>>((const float*)pxpe, wT + 1 * DIM * DIM, bk, (float*)pk);
    k_gemm_mma<<<ggrid, 256, GSMEM>>>((const float*)pxpe, wT + 2 * DIM * DIM, bv, (float*)pv);

    dim3 agrid(SEQ / 64, NH, BATCH);             // (32, 16, 4)
    k_attn_mma<<<agrid, 128, ASMEM>>>();

    k_gemm_mma<<<ggrid, 256, GSMEM>>>((const float*)pattn, wT + 3 * DIM * DIM, bo, (float*)pproj);

    k_ln<<<NTOK, 256>>>(gamma, beta, out);
}

// round 4
// speedup vs baseline: 5.2439x; 1.1330x over previous
#include <cuda_runtime.h>
#include <cstdint>

#define SEQ   2048
#define BATCH 4
#define NTOK  (SEQ * BATCH)      // 8192
#define DIM   1024
#define NH    16
#define HD    64

// ---------------- scratch (device globals per allocation rules) -------------
__device__ float g_xpe [NTOK * DIM];
__device__ float g_q   [NTOK * DIM];
__device__ float g_k   [NTOK * DIM];
__device__ float g_v   [NTOK * DIM];
__device__ float g_attn[NTOK * DIM];
__device__ float g_proj[NTOK * DIM];
__device__ float g_wT  [4][DIM * DIM];   // transposed weights [N,K]

// ---------------- helpers -----------------------------------------------------
__device__ __forceinline__ uint32_t smem_u32(const void* p) {
    uint32_t a;
    asm("{ .reg .u64 t; cvta.to.shared.u64 t, %1; cvt.u32.u64 %0, t; }" : "=r"(a) : "l"(p));
    return a;
}
__device__ __forceinline__ void cp16(uint32_t dst, const void* src) {
    asm volatile("cp.async.cg.shared.global [%0], [%1], 16;" :: "r"(dst), "l"(src));
}
#define CP_COMMIT() asm volatile("cp.async.commit_group;" ::: "memory")
#define CP_WAIT0()  asm volatile("cp.async.wait_group 0;" ::: "memory")

// raw fp32 bits as tf32 operands (HW truncates low mantissa bits)
__device__ __forceinline__ void mma_tf32(float* d, const uint32_t* a, const uint32_t* b) {
    asm volatile(
        "mma.sync.aligned.m16n8k8.row.col.f32.tf32.tf32.f32 "
        "{%0,%1,%2,%3}, {%4,%5,%6,%7}, {%8,%9}, {%0,%1,%2,%3};\n"
        : "+f"(d[0]), "+f"(d[1]), "+f"(d[2]), "+f"(d[3])
        : "r"(a[0]), "r"(a[1]), "r"(a[2]), "r"(a[3]), "r"(b[0]), "r"(b[1]));
}

// ---------------- x + pe ----------------------------------------------------
__global__ void k_addpe(const float* __restrict__ x, const float* __restrict__ pe) {
    int idx = blockIdx.x * 256 + threadIdx.x;
    const float4* x4  = (const float4*)x;
    const float4* pe4 = (const float4*)pe;
    float4*       o4  = (float4*)g_xpe;
    int row = idx >> 8;
    int c   = idx & 255;
    int s   = row & (SEQ - 1);
    float4 a = x4[idx];
    float4 b = pe4[s * 256 + c];
    a.x += b.x; a.y += b.y; a.z += b.z; a.w += b.w;
    o4[idx] = a;
}

// ---------------- weight transpose: out[n,k] = in[k,n] ----------------------
__global__ __launch_bounds__(256) void k_transpose(const float* __restrict__ in,
                                                   float* __restrict__ out) {
    __shared__ float t[32][33];
    int n0 = blockIdx.x * 32, k0 = blockIdx.y * 32;
    int tx = threadIdx.x & 31, ty = threadIdx.x >> 5;
    #pragma unroll
    for (int i = ty; i < 32; i += 8)
        t[i][tx] = in[(size_t)(k0 + i) * DIM + n0 + tx];
    __syncthreads();
    #pragma unroll
    for (int i = ty; i < 32; i += 8)
        out[(size_t)(n0 + i) * DIM + k0 + tx] = t[tx][i];
}

// ---------------- tf32 mma GEMM: C[M,N] = A[M,K] @ Bt[N,K]^T + bias ---------
// 128x128 CTA tile, BK=32, 8 warps (4x2), warp tile 32x64, cp.async dbl-buffer
#define GPAD  36
#define GTILE (128 * GPAD)                 // words per tile
#define GSMEM (4 * GTILE * 4)              // 73728 bytes
#define NC    (DIM / 32)

__global__ __launch_bounds__(256) void k_gemm_mma(
    const float* __restrict__ A, const float* __restrict__ Bt,
    const float* __restrict__ bias, float* __restrict__ C)
{
    extern __shared__ uint32_t sm[];
    const uint32_t smb = smem_u32(sm);
    const int tid  = threadIdx.x;
    const int lane = tid & 31;
    const int wid  = tid >> 5;
    const int wr   = wid & 3;
    const int wc   = wid >> 2;
    const int rowBase = blockIdx.y * 128;
    const int colBase = blockIdx.x * 128;

    const float* Ab = A  + (size_t)rowBase * DIM;
    const float* Bb = Bt + (size_t)colBase * DIM;

    float acc[2][8][4];
    #pragma unroll
    for (int mt = 0; mt < 2; mt++)
        #pragma unroll
        for (int nt = 0; nt < 8; nt++)
            #pragma unroll
            for (int j = 0; j < 4; j++) acc[mt][nt][j] = 0.f;

    auto copy_tile = [&](int buf, int chunk) {
        uint32_t as_ = smb + buf * 2 * GTILE * 4;
        uint32_t bs_ = as_ + GTILE * 4;
        #pragma unroll
        for (int i = 0; i < 4; i++) {
            int idx = i * 256 + tid;
            int r = idx >> 3, c4 = idx & 7;
            uint32_t off = (r * GPAD + c4 * 4) * 4;
            const float* sa = Ab + (size_t)r * DIM + chunk * 32 + c4 * 4;
            const float* sb = Bb + (size_t)r * DIM + chunk * 32 + c4 * 4;
            cp16(as_ + off, sa);
            cp16(bs_ + off, sb);
        }
    };
    auto compute = [&](int buf) {
        const uint32_t* as_ = sm + buf * 2 * GTILE;
        const uint32_t* bs_ = as_ + GTILE;
        #pragma unroll
        for (int kk = 0; kk < 32; kk += 8) {
            uint32_t af[2][4];
            #pragma unroll
            for (int mt = 0; mt < 2; mt++) {
                int r = wr * 32 + mt * 16 + (lane >> 2);
                int c = kk + (lane & 3);
                af[mt][0] = as_[r * GPAD + c];
                af[mt][1] = as_[(r + 8) * GPAD + c];
                af[mt][2] = as_[r * GPAD + c + 4];
                af[mt][3] = as_[(r + 8) * GPAD + c + 4];
            }
            #pragma unroll
            for (int nt = 0; nt < 8; nt++) {
                int n = wc * 64 + nt * 8 + (lane >> 2);
                uint32_t bf[2];
                bf[0] = bs_[n * GPAD + kk + (lane & 3)];
                bf[1] = bs_[n * GPAD + kk + (lane & 3) + 4];
                mma_tf32(acc[0][nt], af[0], bf);
                mma_tf32(acc[1][nt], af[1], bf);
            }
        }
    };

    copy_tile(0, 0); CP_COMMIT();
    CP_WAIT0(); __syncthreads();
    for (int c = 0; c < NC; c++) {
        int b = c & 1;
        if (c + 1 < NC) { copy_tile(b ^ 1, c + 1); CP_COMMIT(); }
        compute(b);
        CP_WAIT0(); __syncthreads();
    }

    #pragma unroll
    for (int mt = 0; mt < 2; mt++) {
        int r = rowBase + wr * 32 + mt * 16 + (lane >> 2);
        #pragma unroll
        for (int nt = 0; nt < 8; nt++) {
            int col = colBase + wc * 64 + nt * 8 + 2 * (lane & 3);
            float2 b2 = *(const float2*)&bias[col];
            float2 o0 = make_float2(acc[mt][nt][0] + b2.x, acc[mt][nt][1] + b2.y);
            float2 o1 = make_float2(acc[mt][nt][2] + b2.x, acc[mt][nt][3] + b2.y);
            *(float2*)&C[(size_t)r * DIM + col]       = o0;
            *(float2*)&C[(size_t)(r + 8) * DIM + col] = o1;
        }
    }
}

// ---------------- flash attention via mma ------------------------------------
// 256 threads / 8 warps, 128 queries per CTA; warp owns 16 q-rows.
// K/V 64-key tiles, cp.async double-buffered.
#define AQS 68
#define AVS 72
#define QW   (128 * AQS)                     // Qs words
#define KVW  (64 * AQS + 64 * AVS)           // per K/V stage
#define OFF_K(b)  (QW + (b) * KVW)
#define OFF_V(b)  (QW + (b) * KVW + 64 * AQS)
#define OFF_P     (QW + 2 * KVW)
#define ASMEM ((QW + 2 * KVW + 128 * AQS) * 4)   // 141312 bytes
#define NT   (SEQ / 64)

__global__ __launch_bounds__(256) void k_attn_mma()
{
    extern __shared__ uint32_t sm[];
    const uint32_t smb = smem_u32(sm);
    uint32_t* Qs = sm;
    uint32_t* Ps = sm + OFF_P;

    const int tid  = threadIdx.x;
    const int lane = tid & 31;
    const int wid  = tid >> 5;
    const int qt = blockIdx.x, h = blockIdx.y, b = blockIdx.z;
    const size_t qbase  = (size_t)(b * SEQ + qt * 128);
    const size_t kvbase = (size_t)(b * SEQ) * DIM + h * 64;

    auto copy_q = [&]() {
        #pragma unroll
        for (int i = 0; i < 8; i++) {
            int idx = i * 256 + tid;
            int r = idx >> 4, c4 = idx & 15;
            cp16(smb + (r * AQS + c4 * 4) * 4,
                 g_q + (qbase + r) * DIM + h * 64 + c4 * 4);
        }
    };
    auto copy_kv = [&](int buf, int kt) {
        uint32_t kb = smb + OFF_K(buf) * 4;
        uint32_t vb = smb + OFF_V(buf) * 4;
        #pragma unroll
        for (int i = 0; i < 4; i++) {
            int idx = i * 256 + tid;
            int r = idx >> 4, c4 = idx & 15;
            size_t g = kvbase + (size_t)(kt * 64 + r) * DIM + c4 * 4;
            cp16(kb + (r * AQS + c4 * 4) * 4, g_k + g);
            cp16(vb + (r * AVS + c4 * 4) * 4, g_v + g);
        }
    };

    copy_q();
    copy_kv(0, 0);
    CP_COMMIT();

    float Oa[8][4];
    #pragma unroll
    for (int nt = 0; nt < 8; nt++)
        #pragma unroll
        for (int j = 0; j < 4; j++) Oa[nt][j] = 0.f;
    float m0 = -1e30f, m1 = -1e30f, l0 = 0.f, l1 = 0.f;

    CP_WAIT0(); __syncthreads();

    for (int kt = 0; kt < NT; kt++) {
        int bu = kt & 1;
        if (kt + 1 < NT) { copy_kv(bu ^ 1, kt + 1); CP_COMMIT(); }

        const uint32_t* Ks = sm + OFF_K(bu);
        const uint32_t* Vs = sm + OFF_V(bu);

        // S = Q @ K^T
        float Sa[8][4];
        #pragma unroll
        for (int nt = 0; nt < 8; nt++)
            #pragma unroll
            for (int j = 0; j < 4; j++) Sa[nt][j] = 0.f;
        #pragma unroll
        for (int kk = 0; kk < 64; kk += 8) {
            uint32_t af[4];
            int r = wid * 16 + (lane >> 2);
            int c = kk + (lane & 3);
            af[0] = Qs[r * AQS + c];
            af[1] = Qs[(r + 8) * AQS + c];
            af[2] = Qs[r * AQS + c + 4];
            af[3] = Qs[(r + 8) * AQS + c + 4];
            #pragma unroll
            for (int nt = 0; nt < 8; nt++) {
                int n = nt * 8 + (lane >> 2);
                uint32_t bf[2];
                bf[0] = Ks[n * AQS + kk + (lane & 3)];
                bf[1] = Ks[n * AQS + kk + (lane & 3) + 4];
                mma_tf32(Sa[nt], af, bf);
            }
        }
        #pragma unroll
        for (int nt = 0; nt < 8; nt++)
            #pragma unroll
            for (int j = 0; j < 4; j++) Sa[nt][j] *= 0.125f;

        // online softmax (rows r0=wid*16+lane/4, r1=r0+8)
        float mx0 = m0, mx1 = m1;
        #pragma unroll
        for (int nt = 0; nt < 8; nt++) {
            mx0 = fmaxf(mx0, fmaxf(Sa[nt][0], Sa[nt][1]));
            mx1 = fmaxf(mx1, fmaxf(Sa[nt][2], Sa[nt][3]));
        }
        #pragma unroll
        for (int o = 1; o <= 2; o <<= 1) {
            mx0 = fmaxf(mx0, __shfl_xor_sync(0xffffffffu, mx0, o));
            mx1 = fmaxf(mx1, __shfl_xor_sync(0xffffffffu, mx1, o));
        }
        float corr0 = __expf(m0 - mx0);
        float corr1 = __expf(m1 - mx1);
        m0 = mx0; m1 = mx1;

        float s0 = 0.f, s1 = 0.f;
        int pr = wid * 16 + (lane >> 2);
        #pragma unroll
        for (int nt = 0; nt < 8; nt++) {
            float p00 = __expf(Sa[nt][0] - m0);
            float p01 = __expf(Sa[nt][1] - m0);
            float p10 = __expf(Sa[nt][2] - m1);
            float p11 = __expf(Sa[nt][3] - m1);
            s0 += p00 + p01; s1 += p10 + p11;
            int col = nt * 8 + 2 * (lane & 3);
            Ps[pr * AQS + col]           = __float_as_uint(p00);
            Ps[pr * AQS + col + 1]       = __float_as_uint(p01);
            Ps[(pr + 8) * AQS + col]     = __float_as_uint(p10);
            Ps[(pr + 8) * AQS + col + 1] = __float_as_uint(p11);
        }
        #pragma unroll
        for (int o = 1; o <= 2; o <<= 1) {
            s0 += __shfl_xor_sync(0xffffffffu, s0, o);
            s1 += __shfl_xor_sync(0xffffffffu, s1, o);
        }
        l0 = l0 * corr0 + s0;
        l1 = l1 * corr1 + s1;
        #pragma unroll
        for (int nt = 0; nt < 8; nt++) {
            Oa[nt][0] *= corr0; Oa[nt][1] *= corr0;
            Oa[nt][2] *= corr1; Oa[nt][3] *= corr1;
        }
        __syncwarp();

        // O += P @ V
        #pragma unroll
        for (int kk = 0; kk < 64; kk += 8) {
            uint32_t af[4];
            int r = wid * 16 + (lane >> 2);
            int c = kk + (lane & 3);
            af[0] = Ps[r * AQS + c];
            af[1] = Ps[(r + 8) * AQS + c];
            af[2] = Ps[r * AQS + c + 4];
            af[3] = Ps[(r + 8) * AQS + c + 4];
            #pragma unroll
            for (int nt = 0; nt < 8; nt++) {
                uint32_t bf[2];
                bf[0] = Vs[(kk + (lane & 3)) * AVS + nt * 8 + (lane >> 2)];
                bf[1] = Vs[(kk + (lane & 3) + 4) * AVS + nt * 8 + (lane >> 2)];
                mma_tf32(Oa[nt], af, bf);
            }
        }

        CP_WAIT0(); __syncthreads();
    }

    float inv0 = 1.f / l0, inv1 = 1.f / l1;
    size_t r = qbase + wid * 16 + (lane >> 2);
    #pragma unroll
    for (int nt = 0; nt < 8; nt++) {
        int col = h * 64 + nt * 8 + 2 * (lane & 3);
        *(float2*)&g_attn[r * DIM + col] =
            make_float2(Oa[nt][0] * inv0, Oa[nt][1] * inv0);
        *(float2*)&g_attn[(r + 8) * DIM + col] =
            make_float2(Oa[nt][2] * inv1, Oa[nt][3] * inv1);
    }
}

// ---------------- residual + layernorm ---------------------------------------
__global__ __launch_bounds__(256) void k_ln(const float* __restrict__ gamma,
                                            const float* __restrict__ beta,
                                            float* __restrict__ out)
{
    __shared__ float ws[8], wss[8];
    const int row = blockIdx.x;
    const int tid = threadIdx.x;

    const float4* p4 = (const float4*)(g_proj + (size_t)row * DIM);
    const float4* x4 = (const float4*)(g_xpe  + (size_t)row * DIM);
    float4 a = p4[tid];
    float4 b = x4[tid];
    float4 hv = make_float4(a.x + b.x, a.y + b.y, a.z + b.z, a.w + b.w);

    float s  = hv.x + hv.y + hv.z + hv.w;
    float ss = hv.x * hv.x + hv.y * hv.y + hv.z * hv.z + hv.w * hv.w;
    #pragma unroll
    for (int o = 16; o; o >>= 1) {
        s  += __shfl_xor_sync(0xffffffffu, s,  o);
        ss += __shfl_xor_sync(0xffffffffu, ss, o);
    }
    int w = tid >> 5;
    if ((tid & 31) == 0) { ws[w] = s; wss[w] = ss; }
    __syncthreads();

    float ts = 0.f, tss = 0.f;
    #pragma unroll
    for (int i = 0; i < 8; i++) { ts += ws[i]; tss += wss[i]; }
    float mean = ts * (1.f / 1024.f);
    float var  = tss * (1.f / 1024.f) - mean * mean;
    float rstd = rsqrtf(var + 1e-5f);

    float4 g  = ((const float4*)gamma)[tid];
    float4 be = ((const float4*)beta)[tid];
    float4 o;
    o.x = (hv.x - mean) * rstd * g.x + be.x;
    o.y = (hv.y - mean) * rstd * g.y + be.y;
    o.z = (hv.z - mean) * rstd * g.z + be.z;
    o.w = (hv.w - mean) * rstd * g.w + be.w;
    ((float4*)out)[(size_t)row * 256 + tid] = o;
}

// ---------------- launch ------------------------------------------------------
extern "C" void kernel_launch(void* const* d_in, const int* in_sizes, int n_in,
                              void* d_out, int out_size)
{
    const float* x     = (const float*)d_in[0];
    const float* wq    = (const float*)d_in[1];
    const float* bq    = (const float*)d_in[2];
    const float* wk    = (const float*)d_in[3];
    const float* bk    = (const float*)d_in[4];
    const float* wv    = (const float*)d_in[5];
    const float* bv    = (const float*)d_in[6];
    const float* wo    = (const float*)d_in[7];
    const float* bo    = (const float*)d_in[8];
    const float* gamma = (const float*)d_in[9];
    const float* beta  = (const float*)d_in[10];
    const float* pe    = (const float*)d_in[11];
    float* out = (float*)d_out;

    void *pxpe, *pq, *pk, *pv, *pattn, *pproj, *pwT;
    cudaGetSymbolAddress(&pxpe,  g_xpe);
    cudaGetSymbolAddress(&pq,    g_q);
    cudaGetSymbolAddress(&pk,    g_k);
    cudaGetSymbolAddress(&pv,    g_v);
    cudaGetSymbolAddress(&pattn, g_attn);
    cudaGetSymbolAddress(&pproj, g_proj);
    cudaGetSymbolAddress(&pwT,   g_wT);
    float* wT = (float*)pwT;

    cudaFuncSetAttribute(k_gemm_mma, cudaFuncAttributeMaxDynamicSharedMemorySize, GSMEM);
    cudaFuncSetAttribute(k_attn_mma, cudaFuncAttributeMaxDynamicSharedMemorySize, ASMEM);

    k_addpe<<<(NTOK * DIM / 4) / 256, 256>>>(x, pe);

    dim3 tgrid(DIM / 32, DIM / 32);
    k_transpose<<<tgrid, 256>>>(wq, wT + 0 * DIM * DIM);
    k_transpose<<<tgrid, 256>>>(wk, wT + 1 * DIM * DIM);
    k_transpose<<<tgrid, 256>>>(wv, wT + 2 * DIM * DIM);
    k_transpose<<<tgrid, 256>>>(wo, wT + 3 * DIM * DIM);

    dim3 ggrid(DIM / 128, NTOK / 128);           // (8, 64)
    k_gemm_mma<<<ggrid, 256, GSMEM>>>((const float*)pxpe, wT + 0 * DIM * DIM, bq, (float*)pq);
    k_gemm_mma<<<ggrid, 256, GSMEM>>>((const float*)pxpe, wT + 1 * DIM * DIM, bk, (float*)pk);
    k_gemm_mma<<<ggrid, 256, GSMEM>>>((const float*)pxpe, wT + 2 * DIM * DIM, bv, (float*)pv);

    dim3 agrid(SEQ / 128, NH, BATCH);            // (16, 16, 4)
    k_attn_mma<<<agrid, 256, ASMEM>>>();

    k_gemm_mma<<<ggrid, 256, GSMEM>>>((const float*)pattn, wT + 3 * DIM * DIM, bo, (float*)pproj);

    k_ln<<<NTOK, 256>>>(gamma, beta, out);
}

// round 5
// speedup vs baseline: 5.5836x; 1.0648x over previous
#include <cuda_runtime.h>
#include <cstdint>

#define SEQ   2048
#define BATCH 4
#define NTOK  (SEQ * BATCH)      // 8192
#define DIM   1024
#define NH    16
#define HD    64

// ---------------- scratch (device globals per allocation rules) -------------
__device__ float g_xpe [NTOK * DIM];
__device__ float g_q   [NTOK * DIM];
__device__ float g_k   [NTOK * DIM];
__device__ float g_v   [NTOK * DIM];
__device__ float g_attn[NTOK * DIM];
__device__ float g_proj[NTOK * DIM];
__device__ float g_wT  [4][DIM * DIM];   // transposed weights [N,K]

// ---------------- helpers -----------------------------------------------------
__device__ __forceinline__ uint32_t smem_u32(const void* p) {
    uint32_t a;
    asm("{ .reg .u64 t; cvta.to.shared.u64 t, %1; cvt.u32.u64 %0, t; }" : "=r"(a) : "l"(p));
    return a;
}
__device__ __forceinline__ void cp16(uint32_t dst, const void* src) {
    asm volatile("cp.async.cg.shared.global [%0], [%1], 16;" :: "r"(dst), "l"(src));
}
#define CP_COMMIT() asm volatile("cp.async.commit_group;" ::: "memory")
#define CP_WAIT0()  asm volatile("cp.async.wait_group 0;" ::: "memory")
#define CP_WAIT1()  asm volatile("cp.async.wait_group 1;" ::: "memory")

// raw fp32 bits as tf32 operands (HW truncates low mantissa bits)
__device__ __forceinline__ void mma_tf32(float* d, const uint32_t* a, const uint32_t* b) {
    asm volatile(
        "mma.sync.aligned.m16n8k8.row.col.f32.tf32.tf32.f32 "
        "{%0,%1,%2,%3}, {%4,%5,%6,%7}, {%8,%9}, {%0,%1,%2,%3};\n"
        : "+f"(d[0]), "+f"(d[1]), "+f"(d[2]), "+f"(d[3])
        : "r"(a[0]), "r"(a[1]), "r"(a[2]), "r"(a[3]), "r"(b[0]), "r"(b[1]));
}

// ---------------- x + pe ----------------------------------------------------
__global__ void k_addpe(const float* __restrict__ x, const float* __restrict__ pe) {
    int idx = blockIdx.x * 256 + threadIdx.x;
    const float4* x4  = (const float4*)x;
    const float4* pe4 = (const float4*)pe;
    float4*       o4  = (float4*)g_xpe;
    int row = idx >> 8;
    int c   = idx & 255;
    int s   = row & (SEQ - 1);
    float4 a = x4[idx];
    float4 b = pe4[s * 256 + c];
    a.x += b.x; a.y += b.y; a.z += b.z; a.w += b.w;
    o4[idx] = a;
}

// ---------------- fused weight transpose (4 weights via blockIdx.z) ----------
__global__ __launch_bounds__(256) void k_transpose4(
    const float* __restrict__ w0, const float* __restrict__ w1,
    const float* __restrict__ w2, const float* __restrict__ w3)
{
    __shared__ float t[32][33];
    const float* in;
    switch (blockIdx.z) {
        case 0: in = w0; break;
        case 1: in = w1; break;
        case 2: in = w2; break;
        default: in = w3; break;
    }
    float* out = g_wT[blockIdx.z];
    int n0 = blockIdx.x * 32, k0 = blockIdx.y * 32;
    int tx = threadIdx.x & 31, ty = threadIdx.x >> 5;
    #pragma unroll
    for (int i = ty; i < 32; i += 8)
        t[i][tx] = in[(size_t)(k0 + i) * DIM + n0 + tx];
    __syncthreads();
    #pragma unroll
    for (int i = ty; i < 32; i += 8)
        out[(size_t)(n0 + i) * DIM + k0 + tx] = t[tx][i];
}

// ---------------- tf32 mma GEMM: C[M,N] = A[M,K] @ Bt[N,K]^T + bias ---------
// 128x128 CTA tile, BK=32, 8 warps (4x2), warp tile 32x64, cp.async dbl-buffer
#define GPAD  36
#define GTILE (128 * GPAD)
#define GSMEM (4 * GTILE * 4)              // 73728 bytes
#define NC    (DIM / 32)

__global__ __launch_bounds__(256) void k_gemm_mma(
    const float* __restrict__ A, const float* __restrict__ Bt,
    const float* __restrict__ bias, float* __restrict__ C)
{
    extern __shared__ uint32_t sm[];
    const uint32_t smb = smem_u32(sm);
    const int tid  = threadIdx.x;
    const int lane = tid & 31;
    const int wid  = tid >> 5;
    const int wr   = wid & 3;
    const int wc   = wid >> 2;
    const int rowBase = blockIdx.y * 128;
    const int colBase = blockIdx.x * 128;

    const float* Ab = A  + (size_t)rowBase * DIM;
    const float* Bb = Bt + (size_t)colBase * DIM;

    float acc[2][8][4];
    #pragma unroll
    for (int mt = 0; mt < 2; mt++)
        #pragma unroll
        for (int nt = 0; nt < 8; nt++)
            #pragma unroll
            for (int j = 0; j < 4; j++) acc[mt][nt][j] = 0.f;

    auto copy_tile = [&](int buf, int chunk) {
        uint32_t as_ = smb + buf * 2 * GTILE * 4;
        uint32_t bs_ = as_ + GTILE * 4;
        #pragma unroll
        for (int i = 0; i < 4; i++) {
            int idx = i * 256 + tid;
            int r = idx >> 3, c4 = idx & 7;
            uint32_t off = (r * GPAD + c4 * 4) * 4;
            cp16(as_ + off, Ab + (size_t)r * DIM + chunk * 32 + c4 * 4);
            cp16(bs_ + off, Bb + (size_t)r * DIM + chunk * 32 + c4 * 4);
        }
    };
    auto compute = [&](int buf) {
        const uint32_t* as_ = sm + buf * 2 * GTILE;
        const uint32_t* bs_ = as_ + GTILE;
        #pragma unroll
        for (int kk = 0; kk < 32; kk += 8) {
            uint32_t af[2][4];
            #pragma unroll
            for (int mt = 0; mt < 2; mt++) {
                int r = wr * 32 + mt * 16 + (lane >> 2);
                int c = kk + (lane & 3);
                af[mt][0] = as_[r * GPAD + c];
                af[mt][1] = as_[(r + 8) * GPAD + c];
                af[mt][2] = as_[r * GPAD + c + 4];
                af[mt][3] = as_[(r + 8) * GPAD + c + 4];
            }
            #pragma unroll
            for (int nt = 0; nt < 8; nt++) {
                int n = wc * 64 + nt * 8 + (lane >> 2);
                uint32_t bf[2];
                bf[0] = bs_[n * GPAD + kk + (lane & 3)];
                bf[1] = bs_[n * GPAD + kk + (lane & 3) + 4];
                mma_tf32(acc[0][nt], af[0], bf);
                mma_tf32(acc[1][nt], af[1], bf);
            }
        }
    };

    copy_tile(0, 0); CP_COMMIT();
    CP_WAIT0(); __syncthreads();
    for (int c = 0; c < NC; c++) {
        int b = c & 1;
        if (c + 1 < NC) { copy_tile(b ^ 1, c + 1); CP_COMMIT(); }
        compute(b);
        CP_WAIT0(); __syncthreads();
    }

    #pragma unroll
    for (int mt = 0; mt < 2; mt++) {
        int r = rowBase + wr * 32 + mt * 16 + (lane >> 2);
        #pragma unroll
        for (int nt = 0; nt < 8; nt++) {
            int col = colBase + wc * 64 + nt * 8 + 2 * (lane & 3);
            float2 b2 = *(const float2*)&bias[col];
            float2 o0 = make_float2(acc[mt][nt][0] + b2.x, acc[mt][nt][1] + b2.y);
            float2 o1 = make_float2(acc[mt][nt][2] + b2.x, acc[mt][nt][3] + b2.y);
            *(float2*)&C[(size_t)r * DIM + col]       = o0;
            *(float2*)&C[(size_t)(r + 8) * DIM + col] = o1;
        }
    }
}

// ---------------- flash attention via mma ------------------------------------
// 256 threads / 8 warps, 128 queries per CTA; warp owns 16 q-rows.
// Single K buffer + single V buffer, pipelined via cp.async group ordering:
// K(t+1) prefetched during softmax/PV(t); V(t+1) prefetched during S(t+1).
#define AQS 68
#define AVS 72
#define OFF_Q  0
#define OFF_KK (128 * AQS)                 // 8704
#define OFF_VV (OFF_KK + 64 * AQS)         // 13056
#define OFF_PP (OFF_VV + 64 * AVS)         // 17664
#define ASMEM  ((OFF_PP + 128 * AQS) * 4)  // 105472 bytes
#define NT   (SEQ / 64)

__global__ __launch_bounds__(256) void k_attn_mma()
{
    extern __shared__ uint32_t sm[];
    const uint32_t smb = smem_u32(sm);
    uint32_t* Qs = sm + OFF_Q;
    uint32_t* Ks = sm + OFF_KK;
    uint32_t* Vs = sm + OFF_VV;
    uint32_t* Ps = sm + OFF_PP;

    const int tid  = threadIdx.x;
    const int lane = tid & 31;
    const int wid  = tid >> 5;
    const int qt = blockIdx.x, h = blockIdx.y, b = blockIdx.z;
    const size_t qbase  = (size_t)(b * SEQ + qt * 128);
    const size_t kvbase = (size_t)(b * SEQ) * DIM + h * 64;

    auto copy_q = [&]() {
        #pragma unroll
        for (int i = 0; i < 8; i++) {
            int idx = i * 256 + tid;
            int r = idx >> 4, c4 = idx & 15;
            cp16(smb + (OFF_Q + r * AQS + c4 * 4) * 4,
                 g_q + (qbase + r) * DIM + h * 64 + c4 * 4);
        }
    };
    auto copy_k = [&](int kt) {
        #pragma unroll
        for (int i = 0; i < 4; i++) {
            int idx = i * 256 + tid;
            int r = idx >> 4, c4 = idx & 15;
            cp16(smb + (OFF_KK + r * AQS + c4 * 4) * 4,
                 g_k + kvbase + (size_t)(kt * 64 + r) * DIM + c4 * 4);
        }
    };
    auto copy_v = [&](int kt) {
        #pragma unroll
        for (int i = 0; i < 4; i++) {
            int idx = i * 256 + tid;
            int r = idx >> 4, c4 = idx & 15;
            cp16(smb + (OFF_VV + r * AVS + c4 * 4) * 4,
                 g_v + kvbase + (size_t)(kt * 64 + r) * DIM + c4 * 4);
        }
    };

    float Oa[8][4];
    #pragma unroll
    for (int nt = 0; nt < 8; nt++)
        #pragma unroll
        for (int j = 0; j < 4; j++) Oa[nt][j] = 0.f;
    float m0 = -1e30f, m1 = -1e30f, l0 = 0.f, l1 = 0.f;

    copy_q(); copy_k(0); CP_COMMIT();       // group: Q+K0
    copy_v(0); CP_COMMIT();                 // group: V0
    CP_WAIT1(); __syncthreads();            // Q + K0 ready; V0 in flight

    for (int kt = 0; kt < NT; kt++) {
        // ---- S = Q @ K^T (K[kt] resident) ----
        float Sa[8][4];
        #pragma unroll
        for (int nt = 0; nt < 8; nt++)
            #pragma unroll
            for (int j = 0; j < 4; j++) Sa[nt][j] = 0.f;
        #pragma unroll
        for (int kk = 0; kk < 64; kk += 8) {
            uint32_t af[4];
            int r = wid * 16 + (lane >> 2);
            int c = kk + (lane & 3);
            af[0] = Qs[r * AQS + c];
            af[1] = Qs[(r + 8) * AQS + c];
            af[2] = Qs[r * AQS + c + 4];
            af[3] = Qs[(r + 8) * AQS + c + 4];
            #pragma unroll
            for (int nt = 0; nt < 8; nt++) {
                int n = nt * 8 + (lane >> 2);
                uint32_t bf[2];
                bf[0] = Ks[n * AQS + kk + (lane & 3)];
                bf[1] = Ks[n * AQS + kk + (lane & 3) + 4];
                mma_tf32(Sa[nt], af, bf);
            }
        }
        __syncthreads();                     // all warps done with K[kt]
        if (kt + 1 < NT) { copy_k(kt + 1); CP_COMMIT(); }

        #pragma unroll
        for (int nt = 0; nt < 8; nt++)
            #pragma unroll
            for (int j = 0; j < 4; j++) Sa[nt][j] *= 0.125f;

        // ---- online softmax ----
        float mx0 = m0, mx1 = m1;
        #pragma unroll
        for (int nt = 0; nt < 8; nt++) {
            mx0 = fmaxf(mx0, fmaxf(Sa[nt][0], Sa[nt][1]));
            mx1 = fmaxf(mx1, fmaxf(Sa[nt][2], Sa[nt][3]));
        }
        #pragma unroll
        for (int o = 1; o <= 2; o <<= 1) {
            mx0 = fmaxf(mx0, __shfl_xor_sync(0xffffffffu, mx0, o));
            mx1 = fmaxf(mx1, __shfl_xor_sync(0xffffffffu, mx1, o));
        }
        float corr0 = __expf(m0 - mx0);
        float corr1 = __expf(m1 - mx1);
        m0 = mx0; m1 = mx1;

        float s0 = 0.f, s1 = 0.f;
        int pr = wid * 16 + (lane >> 2);
        #pragma unroll
        for (int nt = 0; nt < 8; nt++) {
            float p00 = __expf(Sa[nt][0] - m0);
            float p01 = __expf(Sa[nt][1] - m0);
            float p10 = __expf(Sa[nt][2] - m1);
            float p11 = __expf(Sa[nt][3] - m1);
            s0 += p00 + p01; s1 += p10 + p11;
            int col = nt * 8 + 2 * (lane & 3);
            Ps[pr * AQS + col]           = __float_as_uint(p00);
            Ps[pr * AQS + col + 1]       = __float_as_uint(p01);
            Ps[(pr + 8) * AQS + col]     = __float_as_uint(p10);
            Ps[(pr + 8) * AQS + col + 1] = __float_as_uint(p11);
        }
        #pragma unroll
        for (int o = 1; o <= 2; o <<= 1) {
            s0 += __shfl_xor_sync(0xffffffffu, s0, o);
            s1 += __shfl_xor_sync(0xffffffffu, s1, o);
        }
        l0 = l0 * corr0 + s0;
        l1 = l1 * corr1 + s1;
        #pragma unroll
        for (int nt = 0; nt < 8; nt++) {
            Oa[nt][0] *= corr0; Oa[nt][1] *= corr0;
            Oa[nt][2] *= corr1; Oa[nt][3] *= corr1;
        }
        __syncwarp();

        // V[kt] must be resident (oldest outstanding group), K(kt+1) may fly
        if (kt + 1 < NT) { CP_WAIT1(); } else { CP_WAIT0(); }
        __syncthreads();

        // ---- O += P @ V ----
        #pragma unroll
        for (int kk = 0; kk < 64; kk += 8) {
            uint32_t af[4];
            int r = wid * 16 + (lane >> 2);
            int c = kk + (lane & 3);
            af[0] = Ps[r * AQS + c];
            af[1] = Ps[(r + 8) * AQS + c];
            af[2] = Ps[r * AQS + c + 4];
            af[3] = Ps[(r + 8) * AQS + c + 4];
            #pragma unroll
            for (int nt = 0; nt < 8; nt++) {
                uint32_t bf[2];
                bf[0] = Vs[(kk + (lane & 3)) * AVS + nt * 8 + (lane >> 2)];
                bf[1] = Vs[(kk + (lane & 3) + 4) * AVS + nt * 8 + (lane >> 2)];
                mma_tf32(Oa[nt], af, bf);
            }
        }
        __syncthreads();                     // all warps done with V[kt]
        if (kt + 1 < NT) {
            copy_v(kt + 1); CP_COMMIT();
            CP_WAIT1();                      // K(kt+1) ready; V(kt+1) in flight
            __syncthreads();
        }
    }

    float inv0 = 1.f / l0, inv1 = 1.f / l1;
    size_t r = qbase + wid * 16 + (lane >> 2);
    #pragma unroll
    for (int nt = 0; nt < 8; nt++) {
        int col = h * 64 + nt * 8 + 2 * (lane & 3);
        *(float2*)&g_attn[r * DIM + col] =
            make_float2(Oa[nt][0] * inv0, Oa[nt][1] * inv0);
        *(float2*)&g_attn[(r + 8) * DIM + col] =
            make_float2(Oa[nt][2] * inv1, Oa[nt][3] * inv1);
    }
}

// ---------------- residual + layernorm ---------------------------------------
__global__ __launch_bounds__(256) void k_ln(const float* __restrict__ gamma,
                                            const float* __restrict__ beta,
                                            float* __restrict__ out)
{
    __shared__ float ws[8], wss[8];
    const int row = blockIdx.x;
    const int tid = threadIdx.x;

    const float4* p4 = (const float4*)(g_proj + (size_t)row * DIM);
    const float4* x4 = (const float4*)(g_xpe  + (size_t)row * DIM);
    float4 a = p4[tid];
    float4 b = x4[tid];
    float4 hv = make_float4(a.x + b.x, a.y + b.y, a.z + b.z, a.w + b.w);

    float s  = hv.x + hv.y + hv.z + hv.w;
    float ss = hv.x * hv.x + hv.y * hv.y + hv.z * hv.z + hv.w * hv.w;
    #pragma unroll
    for (int o = 16; o; o >>= 1) {
        s  += __shfl_xor_sync(0xffffffffu, s,  o);
        ss += __shfl_xor_sync(0xffffffffu, ss, o);
    }
    int w = tid >> 5;
    if ((tid & 31) == 0) { ws[w] = s; wss[w] = ss; }
    __syncthreads();

    float ts = 0.f, tss = 0.f;
    #pragma unroll
    for (int i = 0; i < 8; i++) { ts += ws[i]; tss += wss[i]; }
    float mean = ts * (1.f / 1024.f);
    float var  = tss * (1.f / 1024.f) - mean * mean;
    float rstd = rsqrtf(var + 1e-5f);

    float4 g  = ((const float4*)gamma)[tid];
    float4 be = ((const float4*)beta)[tid];
    float4 o;
    o.x = (hv.x - mean) * rstd * g.x + be.x;
    o.y = (hv.y - mean) * rstd * g.y + be.y;
    o.z = (hv.z - mean) * rstd * g.z + be.z;
    o.w = (hv.w - mean) * rstd * g.w + be.w;
    ((float4*)out)[(size_t)row * 256 + tid] = o;
}

// ---------------- launch ------------------------------------------------------
extern "C" void kernel_launch(void* const* d_in, const int* in_sizes, int n_in,
                              void* d_out, int out_size)
{
    const float* x     = (const float*)d_in[0];
    const float* wq    = (const float*)d_in[1];
    const float* bq    = (const float*)d_in[2];
    const float* wk    = (const float*)d_in[3];
    const float* bk    = (const float*)d_in[4];
    const float* wv    = (const float*)d_in[5];
    const float* bv    = (const float*)d_in[6];
    const float* wo    = (const float*)d_in[7];
    const float* bo    = (const float*)d_in[8];
    const float* gamma = (const float*)d_in[9];
    const float* beta  = (const float*)d_in[10];
    const float* pe    = (const float*)d_in[11];
    float* out = (float*)d_out;

    void *pxpe, *pq, *pk, *pv, *pattn, *pproj, *pwT;
    cudaGetSymbolAddress(&pxpe,  g_xpe);
    cudaGetSymbolAddress(&pq,    g_q);
    cudaGetSymbolAddress(&pk,    g_k);
    cudaGetSymbolAddress(&pv,    g_v);
    cudaGetSymbolAddress(&pattn, g_attn);
    cudaGetSymbolAddress(&pproj, g_proj);
    cudaGetSymbolAddress(&pwT,   g_wT);
    float* wT = (float*)pwT;

    cudaFuncSetAttribute(k_gemm_mma, cudaFuncAttributeMaxDynamicSharedMemorySize, GSMEM);
    cudaFuncSetAttribute(k_attn_mma, cudaFuncAttributeMaxDynamicSharedMemorySize, ASMEM);

    k_addpe<<<(NTOK * DIM / 4) / 256, 256>>>(x, pe);

    dim3 tgrid(DIM / 32, DIM / 32, 4);
    k_transpose4<<<tgrid, 256>>>(wq, wk, wv, wo);

    dim3 ggrid(DIM / 128, NTOK / 128);           // (8, 64)
    k_gemm_mma<<<ggrid, 256, GSMEM>>>((const float*)pxpe, wT + 0 * DIM * DIM, bq, (float*)pq);
    k_gemm_mma<<<ggrid, 256, GSMEM>>>((const float*)pxpe, wT + 1 * DIM * DIM, bk, (float*)pk);
    k_gemm_mma<<<ggrid, 256, GSMEM>>>((const float*)pxpe, wT + 2 * DIM * DIM, bv, (float*)pv);

    dim3 agrid(SEQ / 128, NH, BATCH);            // (16, 16, 4)
    k_attn_mma<<<agrid, 256, ASMEM>>>();

    k_gemm_mma<<<ggrid, 256, GSMEM>>>((const float*)pattn, wT + 3 * DIM * DIM, bo, (float*)pproj);

    k_ln<<<NTOK, 256>>>(gamma, beta, out);
}